// round 13
// baseline (speedup 1.0000x reference)
#include <cuda_runtime.h>
#include <math.h>

#define HS 1024
#define SS 2048
#define VS 50257
#define NB 148
#define NT 1024
#define NWB 32                      // warps per block
#define NWARPS (NB * NWB)           // 4736
#define CW 28                       // compute (streaming) warps per block
#define ATW 4                       // attention warps per block (tid 896..1023)
#define AWN (NB * ATW)              // 592 attention warps chip-wide
#define CHS ((SS + NB - 1) / NB)    // 14 s-rows per block (context slice)
#define CHV ((VS + NB - 1) / NB)    // 340 logit rows per block (ph9c subtract)
#define CHH ((HS + NB - 1) / NB)    // 7 ctx columns per block (partial reduce)
#define RPW 4                       // rows per steal

// ---------------- scratch (device globals; no allocation allowed) -------------
__device__ float g_gi[3 * HS];
__device__ float g_gh[3 * HS];
__device__ float g_gi2[3 * HS];
__device__ float g_gh2[3 * HS];
__device__ float g_energ[SS];
__device__ float g_ctx[HS];
__device__ float g_part[NB][HS];         // per-block context partials (deterministic)
__device__ float g_pm[NB];
__device__ float g_ps[NB];
__device__ unsigned g_workA;             // half-A row counter (reset each launch)
__device__ unsigned g_workB;             // half-B row counter
__device__ volatile unsigned g_bar_gen;  // statically 0
__device__ unsigned g_bar_cnt;
__device__ volatile unsigned g_abar_gen; // attn-only barrier
__device__ unsigned g_abar_cnt;

// ---------------- full grid barrier (all 148 blocks, all threads) -------------
__device__ __forceinline__ void grid_barrier() {
    __syncthreads();
    if (threadIdx.x == 0) {
        __threadfence();
        unsigned gen = g_bar_gen;
        if (atomicAdd(&g_bar_cnt, 1u) == NB - 1) {
            g_bar_cnt = 0;
            __threadfence();
            g_bar_gen = gen + 1;
        } else {
            while (g_bar_gen == gen) __nanosleep(32);
            __threadfence();
        }
    }
    __syncthreads();
}

// ---------------- attn-warps-only grid barrier (128 threads/block) ------------
__device__ __forceinline__ void attn_grid_barrier() {
    asm volatile("bar.sync 1, 128;" ::: "memory");
    if (threadIdx.x == CW * 32) {
        __threadfence();
        unsigned gen = g_abar_gen;
        if (atomicAdd(&g_abar_cnt, 1u) == NB - 1) {
            g_abar_cnt = 0;
            __threadfence();
            g_abar_gen = gen + 1;
        } else {
            while (g_abar_gen == gen) __nanosleep(32);
            __threadfence();
        }
    }
    asm volatile("bar.sync 1, 128;" ::: "memory");
}

// ---------------- reductions --------------------------------------------------
__device__ __forceinline__ float warpSum(float v) {
    #pragma unroll
    for (int o = 16; o > 0; o >>= 1) v += __shfl_down_sync(0xffffffffu, v, o);
    return v;
}
__device__ __forceinline__ float warpMax(float v) {
    #pragma unroll
    for (int o = 16; o > 0; o >>= 1) v = fmaxf(v, __shfl_down_sync(0xffffffffu, v, o));
    return v;
}
__device__ __forceinline__ float blockSum(float v, float* sm) {  // thread 0 valid
    int lane = threadIdx.x & 31, wid = threadIdx.x >> 5;
    v = warpSum(v);
    if (lane == 0) sm[wid] = v;
    __syncthreads();
    float r = (threadIdx.x < NWB) ? sm[threadIdx.x] : 0.0f;
    __syncthreads();
    if (wid == 0) r = warpSum(r);
    return r;
}
__device__ __forceinline__ float blockMax(float v, float* sm) {  // thread 0 valid
    int lane = threadIdx.x & 31, wid = threadIdx.x >> 5;
    v = warpMax(v);
    if (lane == 0) sm[wid] = v;
    __syncthreads();
    float r = (threadIdx.x < NWB) ? sm[threadIdx.x] : -INFINITY;
    __syncthreads();
    if (wid == 0) r = warpMax(r);
    return r;
}

__device__ __forceinline__ float fma4(float4 w, float4 x, float a) {
    return fmaf(w.x, x.x, fmaf(w.y, x.y, fmaf(w.z, x.z, fmaf(w.w, x.w, a))));
}
__device__ __forceinline__ float sigmoidf_(float x) { return 1.0f / (1.0f + expf(-x)); }

// 2048-col dot: streamed W row (__ldcs) . x (smem float4[512])
__device__ __forceinline__ float dot2048s(const float4* __restrict__ Wr,
                                          const float4* __restrict__ sx, int lane) {
    float a0 = 0.f, a1 = 0.f, a2 = 0.f, a3 = 0.f;
    #pragma unroll
    for (int i = 0; i < 4; i++) {
        int idx = lane + 128 * i;
        float4 w0 = __ldcs(Wr + idx),       x0 = sx[idx];
        float4 w1 = __ldcs(Wr + idx + 32),  x1 = sx[idx + 32];
        float4 w2 = __ldcs(Wr + idx + 64),  x2 = sx[idx + 64];
        float4 w3 = __ldcs(Wr + idx + 96),  x3 = sx[idx + 96];
        a0 = fma4(w0, x0, a0); a1 = fma4(w1, x1, a1);
        a2 = fma4(w2, x2, a2); a3 = fma4(w3, x3, a3);
    }
    return warpSum((a0 + a1) + (a2 + a3));
}

// 1024-col dot: cached row (__ldg) . x (smem float4[256]) — used for enc
__device__ __forceinline__ float dot1024(const float4* __restrict__ Wr,
                                         const float4* __restrict__ sx, int lane) {
    float a0 = 0.f, a1 = 0.f, a2 = 0.f, a3 = 0.f;
    #pragma unroll
    for (int i = 0; i < 2; i++) {
        int idx = lane + 128 * i;
        float4 w0 = __ldg(Wr + idx),       x0 = sx[idx];
        float4 w1 = __ldg(Wr + idx + 32),  x1 = sx[idx + 32];
        float4 w2 = __ldg(Wr + idx + 64),  x2 = sx[idx + 64];
        float4 w3 = __ldg(Wr + idx + 96),  x3 = sx[idx + 96];
        a0 = fma4(w0, x0, a0); a1 = fma4(w1, x1, a1);
        a2 = fma4(w2, x2, a2); a3 = fma4(w3, x3, a3);
    }
    return warpSum((a0 + a1) + (a2 + a3));
}

// 1024-col dot: streamed W row (__ldcs) . x (smem) — GRU weights
__device__ __forceinline__ float dot1024s(const float4* __restrict__ Wr,
                                          const float4* __restrict__ sx, int lane) {
    float a0 = 0.f, a1 = 0.f, a2 = 0.f, a3 = 0.f;
    #pragma unroll
    for (int i = 0; i < 2; i++) {
        int idx = lane + 128 * i;
        float4 w0 = __ldcs(Wr + idx),       x0 = sx[idx];
        float4 w1 = __ldcs(Wr + idx + 32),  x1 = sx[idx + 32];
        float4 w2 = __ldcs(Wr + idx + 64),  x2 = sx[idx + 64];
        float4 w3 = __ldcs(Wr + idx + 96),  x3 = sx[idx + 96];
        a0 = fma4(w0, x0, a0); a1 = fma4(w1, x1, a1);
        a2 = fma4(w2, x2, a2); a3 = fma4(w3, x3, a3);
    }
    return warpSum((a0 + a1) + (a2 + a3));
}

// single 1024-col half-row dot against register x-cache
__device__ __forceinline__ float dotrow(const float4* __restrict__ Wr,
                                        const float4 xr[8], int lane) {
    float a = 0.f;
    #pragma unroll
    for (int k = 0; k < 8; k++) a = fma4(__ldcs(Wr + lane + 32 * k), xr[k], a);
    return warpSum(a);
}

// work-stealing W_out half-sweep.  ADD=false: write logit + bias (half-A).
// ADD=true: accumulate ctx half and maintain lane-0 online (m, s) softmax stats.
template <bool ADD>
__device__ __forceinline__ void sweep_steal(unsigned* ctr,
        const float* __restrict__ Wout, int coloff,
        const float* __restrict__ bout, float* __restrict__ out_logits,
        const float4 xr[8], int lane, float& m, float& s) {
    for (;;) {
        unsigned r0u = 0;
        if (lane == 0) r0u = atomicAdd(ctr, (unsigned)RPW);
        r0u = __shfl_sync(0xffffffffu, r0u, 0);
        if (r0u >= VS) break;
        int r0 = (int)r0u;
        int rend = min(r0 + RPW, VS);
        int r = r0;
        for (; r + 1 < rend; r += 2) {
            const float4* WA = (const float4*)(Wout + (size_t)r * (2 * HS) + coloff);
            const float4* WB = (const float4*)(Wout + (size_t)(r + 1) * (2 * HS) + coloff);
            float aA = 0.f, aB = 0.f;
            #pragma unroll
            for (int k = 0; k < 8; k++) {
                float4 wA = __ldcs(WA + lane + 32 * k);
                float4 wB = __ldcs(WB + lane + 32 * k);
                aA = fma4(wA, xr[k], aA);
                aB = fma4(wB, xr[k], aB);
            }
            aA = warpSum(aA);
            aB = warpSum(aB);
            if (lane == 0) {
                if (ADD) {
                    float vA = out_logits[r] + aA;
                    float vB = out_logits[r + 1] + aB;
                    out_logits[r] = vA;
                    out_logits[r + 1] = vB;
                    float mn = fmaxf(m, fmaxf(vA, vB));
                    s = s * expf(m - mn) + expf(vA - mn) + expf(vB - mn);
                    m = mn;
                } else {
                    out_logits[r]     = aA + __ldg(bout + r);
                    out_logits[r + 1] = aB + __ldg(bout + r + 1);
                }
            }
        }
        if (r < rend) {
            float a = dotrow((const float4*)(Wout + (size_t)r * (2 * HS) + coloff), xr, lane);
            if (lane == 0) {
                if (ADD) {
                    float v = out_logits[r] + a;
                    out_logits[r] = v;
                    float mn = fmaxf(m, v);
                    s = s * expf(m - mn) + expf(v - mn);
                    m = mn;
                } else {
                    out_logits[r] = a + __ldg(bout + r);
                }
            }
        }
    }
}

// ---------------- the single fused kernel -------------------------------------
__global__ void __launch_bounds__(NT, 1)
fused_seq2seq(const int* __restrict__ word,
              const float* __restrict__ ctx_in,
              const float* __restrict__ hid_in,     // (2, H)
              const float* __restrict__ enc,        // (S, H)
              const float* __restrict__ emb,
              const float* __restrict__ Wih0, const float* __restrict__ Whh0,
              const float* __restrict__ bih0, const float* __restrict__ bhh0,
              const float* __restrict__ Wih1, const float* __restrict__ Whh1,
              const float* __restrict__ bih1, const float* __restrict__ bhh1,
              const float* __restrict__ Wout, const float* __restrict__ bout,
              float* __restrict__ out_logits, float* __restrict__ out_ctx,
              float* __restrict__ out_hid0, float* __restrict__ out_hid1,
              float* __restrict__ out_attn) {
    __shared__ float4 s_x4[512];            // 8 KB x buffer (2048 floats)
    __shared__ float4 s_h4[256];            // 4 KB secondary x buffer
    __shared__ float  s_red[32];
    __shared__ float  s_m[NWB], s_s[NWB];   // per-warp online softmax stats
    __shared__ float  s_bc;
    __shared__ float  s_w[CHS];
    __shared__ float  s_am[ATW], s_as[ATW];

    float* s_x = (float*)s_x4;
    float* s_h = (float*)s_h4;

    const int tid  = threadIdx.x;
    const int lane = tid & 31;
    const int wid  = tid >> 5;
    const int gw   = blockIdx.x * NWB + wid;

    // ── ph1: layer-0 matvecs + hoisted Whh1·h1prev (input-only deps) ──
    s_x[tid]      = emb[(size_t)word[0] * HS + tid];
    s_x[HS + tid] = ctx_in[tid];
    s_h[tid]      = hid_in[tid];
    __syncthreads();
    for (int t = gw; t < 9 * HS; t += NWARPS) {
        if (t < 3 * HS) {
            float a = dot2048s((const float4*)(Wih0 + (size_t)t * (2 * HS)), s_x4, lane);
            if (lane == 0) g_gi[t] = a + __ldg(bih0 + t);
        } else if (t < 6 * HS) {
            int row = t - 3 * HS;
            float a = dot1024s((const float4*)(Whh0 + (size_t)row * HS), s_h4, lane);
            if (lane == 0) g_gh[row] = a + __ldg(bhh0 + row);
        } else {
            int row = t - 6 * HS;
            const float4* h1p = (const float4*)(hid_in + HS);
            float a0 = 0.f, a1 = 0.f, a2 = 0.f, a3 = 0.f;
            const float4* Wr = (const float4*)(Whh1 + (size_t)row * HS);
            #pragma unroll
            for (int i = 0; i < 2; i++) {
                int idx = lane + 128 * i;
                float4 w0 = __ldcs(Wr + idx),       x0 = __ldg(h1p + idx);
                float4 w1 = __ldcs(Wr + idx + 32),  x1 = __ldg(h1p + idx + 32);
                float4 w2 = __ldcs(Wr + idx + 64),  x2 = __ldg(h1p + idx + 64);
                float4 w3 = __ldcs(Wr + idx + 96),  x3 = __ldg(h1p + idx + 96);
                a0 = fma4(w0, x0, a0); a1 = fma4(w1, x1, a1);
                a2 = fma4(w2, x2, a2); a3 = fma4(w3, x3, a3);
            }
            float a = warpSum((a0 + a1) + (a2 + a3));
            if (lane == 0) g_gh2[row] = a + __ldg(bhh1 + row);
        }
    }
    grid_barrier();  // B1

    // ── ph2: redundant layer-0 gates -> h0 in s_x[0:H) ──
    {
        float r = sigmoidf_(g_gi[tid] + g_gh[tid]);
        float z = sigmoidf_(g_gi[HS + tid] + g_gh[HS + tid]);
        float n = tanhf(g_gi[2 * HS + tid] + r * g_gh[2 * HS + tid]);
        float h = (1.0f - z) * n + z * hid_in[tid];
        if (blockIdx.x == 0) out_hid0[tid] = h;
        __syncthreads();
        s_x[tid] = h;
    }
    __syncthreads();

    // ── ph3: layer-1 input matvec only ──
    for (int t = gw; t < 3 * HS; t += NWARPS) {
        float a = dot1024s((const float4*)(Wih1 + (size_t)t * HS), s_x4, lane);
        if (lane == 0) g_gi2[t] = a + __ldg(bih1 + t);
    }
    grid_barrier();  // B3

    // ── ph4: redundant layer-1 gates -> h1 in s_x[0:H) ──
    {
        float r = sigmoidf_(g_gi2[tid] + g_gh2[tid]);
        float z = sigmoidf_(g_gi2[HS + tid] + g_gh2[HS + tid]);
        float n = tanhf(g_gi2[2 * HS + tid] + r * g_gh2[2 * HS + tid]);
        float h = (1.0f - z) * n + z * hid_in[HS + tid];
        if (blockIdx.x == 0) out_hid1[tid] = h;
        __syncthreads();
        s_x[tid] = h;
    }
    __syncthreads();   // h1 visible

    float dm = -INFINITY, ds = 0.0f;   // lane-0 online softmax stats (half-B)

    // ═══ WARP SPECIALIZATION: stealing W_out·h1 sweep ∥ attention chain ═══
    if (wid < CW) {
        float4 xr[8];
        #pragma unroll
        for (int k = 0; k < 8; k++) xr[k] = s_x4[lane + 32 * k];
        sweep_steal<false>(&g_workA, Wout, 0, bout, out_logits, xr, lane, dm, ds);
    } else {
        const int tid2 = tid - CW * 32;        // 0..127
        const int awid = wid - CW;             // 0..3
        const int aw   = blockIdx.x * ATW + awid;

        for (int t = aw; t < SS; t += AWN) {
            float a = dot1024((const float4*)(enc + (size_t)t * HS), s_x4, lane);
            if (lane == 0) g_energ[t] = a;
        }
        attn_grid_barrier();   // A1: all energies ready

        float e[16];
        float ml = -INFINITY;
        #pragma unroll
        for (int j = 0; j < 16; j++) {
            e[j] = g_energ[tid2 + 128 * j];
            ml = fmaxf(ml, e[j]);
        }
        ml = warpMax(ml);
        if (lane == 0) s_am[awid] = ml;
        asm volatile("bar.sync 1, 128;" ::: "memory");
        float mx = fmaxf(fmaxf(s_am[0], s_am[1]), fmaxf(s_am[2], s_am[3]));
        float sl = 0.0f;
        #pragma unroll
        for (int j = 0; j < 16; j++) sl += expf(e[j] - mx);
        sl = warpSum(sl);
        if (lane == 0) s_as[awid] = sl;
        asm volatile("bar.sync 1, 128;" ::: "memory");
        float inv = 1.0f / (s_as[0] + s_as[1] + s_as[2] + s_as[3]);

        int s0 = blockIdx.x * CHS;
        int ns = min(CHS, SS - s0); if (ns < 0) ns = 0;
        if (tid2 < ns) {
            float wv = expf(g_energ[s0 + tid2] - mx) * inv;
            s_w[tid2] = wv;
            out_attn[s0 + tid2] = wv;
        }
        asm volatile("bar.sync 1, 128;" ::: "memory");

        {
            int c = tid2 * 8;
            float acc[8] = {0,0,0,0,0,0,0,0};
            for (int j = 0; j < ns; j++) {
                float wv = s_w[j];
                const float4* ep = (const float4*)(enc + (size_t)(s0 + j) * HS + c);
                float4 e0 = __ldg(ep), e1 = __ldg(ep + 1);
                acc[0] = fmaf(wv, e0.x, acc[0]); acc[1] = fmaf(wv, e0.y, acc[1]);
                acc[2] = fmaf(wv, e0.z, acc[2]); acc[3] = fmaf(wv, e0.w, acc[3]);
                acc[4] = fmaf(wv, e1.x, acc[4]); acc[5] = fmaf(wv, e1.y, acc[5]);
                acc[6] = fmaf(wv, e1.z, acc[6]); acc[7] = fmaf(wv, e1.w, acc[7]);
            }
            float* gp = &g_part[blockIdx.x][c];
            #pragma unroll
            for (int k = 0; k < 8; k++) gp[k] = acc[k];
        }
        attn_grid_barrier();   // A2: all partials ready

        if (tid2 < CHH) {
            int c = blockIdx.x * CHH + tid2;
            if (c < HS) {
                float s = 0.0f;
                #pragma unroll 4
                for (int b = 0; b < NB; b++) s += g_part[b][c];
                g_ctx[c] = s;
                out_ctx[c] = s;
            }
        }
        attn_grid_barrier();   // A3: g_ctx fully published chip-wide

        // join the half-A sweep with remaining capacity (h1 still in s_x)
        float4 xr[8];
        #pragma unroll
        for (int k = 0; k < 8; k++) xr[k] = s_x4[lane + 32 * k];
        sweep_steal<false>(&g_workA, Wout, 0, bout, out_logits, xr, lane, dm, ds);
    }
    grid_barrier();  // BH: ALL half-A rows written chip-wide; ctx ready

    // ── half-B: logits += W_out[row, 1024:2048] . ctx — stealing, all warps ──
    {
        s_x[tid] = g_ctx[tid];
        __syncthreads();
        float4 xr[8];
        #pragma unroll
        for (int k = 0; k < 8; k++) xr[k] = s_x4[lane + 32 * k];
        sweep_steal<true>(&g_workB, Wout, HS, nullptr, out_logits, xr, lane, dm, ds);

        // block-combine per-warp online (m, s) -> g_pm/g_ps
        if (lane == 0) { s_m[wid] = dm; s_s[wid] = ds; }
        __syncthreads();
        if (wid == 0) {
            float m = s_m[lane];          // 32 warps
            float M = warpMax(m);
            M = __shfl_sync(0xffffffffu, M, 0);
            float p = s_s[lane] * expf(m - M);   // exp(-inf - M) = 0 when warp idle
            float S = warpSum(p);
            if (lane == 0) { g_pm[blockIdx.x] = M; g_ps[blockIdx.x] = S; }
        }
    }
    grid_barrier();  // B9: all logits + all (m,s) published

    // ── ph9b: redundant combine of 148 partials; subtract over static range ──
    {
        if (blockIdx.x == 0 && tid == 0) { g_workA = 0u; g_workB = 0u; }  // replay reset
        float m = (tid < NB) ? g_pm[tid] : -INFINITY;
        float M = blockMax(m, s_red);
        if (tid == 0) s_bc = M;
        __syncthreads();
        float Mx = s_bc;
        float p = (tid < NB) ? g_ps[tid] * expf(g_pm[tid] - Mx) : 0.0f;
        float S = blockSum(p, s_red);
        if (tid == 0) s_bc = Mx + logf(S);
        __syncthreads();
        float lse = s_bc;
        int base  = blockIdx.x * CHV;
        int nrows = min(CHV, VS - base);
        if (tid < nrows) out_logits[base + tid] -= lse;
    }
}

// ---------------- launch ------------------------------------------------------
extern "C" void kernel_launch(void* const* d_in, const int* in_sizes, int n_in,
                              void* d_out, int out_size) {
    const int*   word         = (const int*)  d_in[0];
    const float* last_context = (const float*)d_in[1];
    const float* last_hidden  = (const float*)d_in[2];
    const float* enc          = (const float*)d_in[3];
    const float* emb          = (const float*)d_in[4];
    const float* W_ih0        = (const float*)d_in[5];
    const float* W_hh0        = (const float*)d_in[6];
    const float* b_ih0        = (const float*)d_in[7];
    const float* b_hh0        = (const float*)d_in[8];
    const float* W_ih1        = (const float*)d_in[9];
    const float* W_hh1        = (const float*)d_in[10];
    const float* b_ih1        = (const float*)d_in[11];
    const float* b_hh1        = (const float*)d_in[12];
    const float* W_out        = (const float*)d_in[13];
    const float* b_out        = (const float*)d_in[14];

    float* out = (float*)d_out;
    float* out_logits = out;                 // V
    float* out_ctx    = out + VS;            // H
    float* out_hid0   = out + VS + HS;       // H
    float* out_hid1   = out + VS + 2 * HS;   // H
    float* out_attn   = out + VS + 3 * HS;   // S

    fused_seq2seq<<<NB, NT>>>(word, last_context, last_hidden, enc, emb,
                              W_ih0, W_hh0, b_ih0, b_hh0,
                              W_ih1, W_hh1, b_ih1, b_hh1,
                              W_out, b_out,
                              out_logits, out_ctx, out_hid0, out_hid1, out_attn);
}